// round 1
// baseline (speedup 1.0000x reference)
#include <cuda_runtime.h>

// Problem constants (B, S, K) = (512, 2048, 17)
#define BB 512
#define SS 2048
#define KK 17
#define SK (SS * KK)

__global__ __launch_bounds__(128) void crf_kernel(
    const float* __restrict__ em,      // [B,S,K]
    const float* __restrict__ startT,  // [K]
    const float* __restrict__ endT,    // [K]
    const float* __restrict__ trans,   // [K,K]
    const int*   __restrict__ labels,  // [B,S]
    const int*   __restrict__ attn,    // [B,S]
    float* __restrict__ out,           // [0]=loss, [1..]=emissions copy
    int copy_emissions)
{
    const int b   = blockIdx.x;
    const int tid = threadIdx.x;
    const float* emb = em + (size_t)b * SK;
    const int*   lab = labels + (size_t)b * SS;
    const int*   msk = attn   + (size_t)b * SS;

    // --- warps 1..3: stream-copy this sequence's emissions into the output ---
    if (tid >= 32) {
        if (copy_emissions) {
            float* dst = out + 1 + (size_t)b * SK;
            for (int i = tid - 32; i < SK; i += 96)
                dst[i] = emb[i];
        }
        return;
    }

    // --- warp 0: numerator + forward scan (linear-space with carried scale) ---
    const int lane = tid;

    __shared__ float    abuf[2][20];        // 20-float stride keeps rows 16B aligned
    __shared__ unsigned mask_bits[SS / 32];

    // exp(transitions) column for this lane's state j
    float w[17];
    #pragma unroll
    for (int i = 0; i < 17; i++)
        w[i] = (lane < KK) ? __expf(trans[i * KK + lane]) : 0.0f;

    // ---- numerator pass + mask bit packing + seq-end stats ----
    float numv = 0.0f;
    int cnt = 0, lastidx = 0;
    for (int t = lane; t < SS; t += 32) {
        int lt = lab[t];
        int m  = (msk[t] != 0) && (lt >= 0);
        unsigned bal = __ballot_sync(0xffffffffu, m);
        if (lane == 0) mask_bits[t >> 5] = bal;
        if (m) {
            cnt++;
            lastidx = t;
            if (t > 0) {
                int ltc = (lt == -100) ? 0 : lt;
                int lp  = lab[t - 1];
                int lpc = (lp == -100) ? 0 : lp;
                numv += trans[lpc * KK + ltc] + emb[t * KK + ltc];
            }
        }
    }
    #pragma unroll
    for (int o = 16; o; o >>= 1) {
        numv += __shfl_xor_sync(0xffffffffu, numv, o);
        cnt  += __shfl_xor_sync(0xffffffffu, cnt,  o);
        lastidx = max(lastidx, __shfl_xor_sync(0xffffffffu, lastidx, o));
    }
    {
        int l0  = lab[0];
        int l0c = (l0 == -100) ? 0 : l0;
        int se  = max(cnt - 1, 0);
        int le  = lab[se];
        int lec = (le == -100) ? 0 : le;
        numv += startT[l0c] + emb[l0c] + endT[lec];
    }
    __syncwarp();  // mask_bits visible to all lanes

    // ---- alpha_0 in linear space ----
    float al = (lane < KK) ? (startT[lane] + emb[lane]) : -1e30f;
    float M = al;
    #pragma unroll
    for (int o = 16; o; o >>= 1)
        M = fmaxf(M, __shfl_xor_sync(0xffffffffu, M, o));
    float a = (lane < KK) ? __expf(al - M) : 0.0f;
    if (lane < KK) abuf[0][lane] = a;
    __syncwarp();

    // ---- forward scan: a_{t} = (a_{t-1} . expW) * exp(e_t), renorm every 8 ----
    int cur = 0;
    unsigned mword = mask_bits[0];
    float e_pref = (lane < KK && lastidx >= 1) ? __ldg(&emb[KK + lane]) : 0.0f;

    for (int t = 1; t <= lastidx; ++t) {
        float e_cur = e_pref;
        if (t + 1 <= lastidx && lane < KK)
            e_pref = __ldg(&emb[(t + 1) * KK + lane]);
        if ((t & 31) == 0) mword = mask_bits[t >> 5];
        bool m = (mword >> (t & 31)) & 1u;

        float4 v0 = *(const float4*)&abuf[cur][0];
        float4 v1 = *(const float4*)&abuf[cur][4];
        float4 v2 = *(const float4*)&abuf[cur][8];
        float4 v3 = *(const float4*)&abuf[cur][12];
        float  a16 = abuf[cur][16];

        float s0 = v0.x * w[0];
        float s1 = v0.y * w[1];
        float s2 = v0.z * w[2];
        float s3 = v0.w * w[3];
        s0 = fmaf(v1.x, w[4],  s0);
        s1 = fmaf(v1.y, w[5],  s1);
        s2 = fmaf(v1.z, w[6],  s2);
        s3 = fmaf(v1.w, w[7],  s3);
        s0 = fmaf(v2.x, w[8],  s0);
        s1 = fmaf(v2.y, w[9],  s1);
        s2 = fmaf(v2.z, w[10], s2);
        s3 = fmaf(v2.w, w[11], s3);
        s0 = fmaf(v3.x, w[12], s0);
        s1 = fmaf(v3.y, w[13], s1);
        s2 = fmaf(v3.z, w[14], s2);
        s3 = fmaf(v3.w, w[15], s3);
        s0 = fmaf(a16,  w[16], s0);
        float s = (s0 + s1) + (s2 + s3);

        float g = __expf(e_cur);
        float anew = s * g;
        if (m) a = anew;                 // mask is uniform across lanes

        if ((t & 7) == 0) {              // renormalize carried scale
            float r = a;
            #pragma unroll
            for (int o = 16; o; o >>= 1)
                r = fmaxf(r, __shfl_xor_sync(0xffffffffu, r, o));
            float inv = 1.0f / r;
            a *= inv;
            M += __logf(r);
        }
        if (lane < KK) abuf[cur ^ 1][lane] = a;
        __syncwarp();
        cur ^= 1;
    }

    // ---- log_z = M + log( sum_j a_j * exp(end_j) ) ----
    float zterm = (lane < KK) ? a * __expf(endT[lane]) : 0.0f;
    #pragma unroll
    for (int o = 16; o; o >>= 1)
        zterm += __shfl_xor_sync(0xffffffffu, zterm, o);
    float logz = M + __logf(zterm);

    if (lane == 0)
        atomicAdd(out, (logz - numv) * (1.0f / (float)BB));  // -mean(llh)
}

extern "C" void kernel_launch(void* const* d_in, const int* in_sizes, int n_in,
                              void* d_out, int out_size)
{
    const float* em  = (const float*)d_in[0];
    const float* st  = (const float*)d_in[1];
    const float* en  = (const float*)d_in[2];
    const float* tr  = (const float*)d_in[3];
    const int*   lab = (const int*)d_in[4];
    const int*   att = (const int*)d_in[5];
    float* out = (float*)d_out;

    int copy = (out_size > in_sizes[0]) ? 1 : 0;

    cudaMemsetAsync(d_out, 0, sizeof(float), 0);
    crf_kernel<<<BB, 128>>>(em, st, en, tr, lab, att, out, copy);
}

// round 2
// speedup vs baseline: 1.8793x; 1.8793x over previous
#include <cuda_runtime.h>

// Problem constants (B, S, K) = (512, 2048, 17)
#define BB 512
#define SS 2048
#define KK 17
#define SK (SS * KK)
#define TILE 32            // scan steps per emission prefetch tile
#define TILEF (TILE * KK)  // 544 floats per tile

__global__ __launch_bounds__(128) void crf_kernel(
    const float* __restrict__ em,      // [B,S,K]
    const float* __restrict__ startT,  // [K]
    const float* __restrict__ endT,    // [K]
    const float* __restrict__ trans,   // [K,K]
    const int*   __restrict__ labels,  // [B,S]
    const int*   __restrict__ attn,    // [B,S]
    float* __restrict__ out,           // [0]=loss, [1..]=emissions copy
    int copy_emissions)
{
    const int b   = blockIdx.x;
    const int tid = threadIdx.x;
    const float* emb = em + (size_t)b * SK;
    const int*   lab = labels + (size_t)b * SS;
    const int*   msk = attn   + (size_t)b * SS;

    // --- warps 1..3: stream-copy this sequence's emissions into the output ---
    if (tid >= 32) {
        if (copy_emissions) {
            const float4* s4 = (const float4*)emb;
            float* dst = out + 1 + (size_t)b * SK;   // 4B-aligned only -> scalar stores
            #pragma unroll 4
            for (int i = tid - 32; i < SK / 4; i += 96) {
                float4 v = s4[i];
                dst[4 * i + 0] = v.x;
                dst[4 * i + 1] = v.y;
                dst[4 * i + 2] = v.z;
                dst[4 * i + 3] = v.w;
            }
        }
        return;
    }

    // --- warp 0: numerator + forward scan ---
    const int lane = tid;

    __shared__ float    tbuf[KK * KK];       // raw transitions
    __shared__ float    ebuf[2][TILEF];      // emission tile double-buffer
    __shared__ unsigned mask_bits[SS / 32];

    for (int i = lane; i < KK * KK; i += 32)
        tbuf[i] = trans[i];
    __syncwarp();

    // exp(transitions) column for this lane's state j
    float w[KK];
    #pragma unroll
    for (int i = 0; i < KK; i++)
        w[i] = (lane < KK) ? __expf(tbuf[i * KK + lane]) : 0.0f;

    // ---- numerator pass + mask bit packing + seq-end stats ----
    float numv = 0.0f;
    int cnt = 0, lastidx = 0;
    #pragma unroll 4
    for (int t = lane; t < SS; t += 32) {
        int lt = lab[t];
        int m  = (msk[t] != 0) && (lt >= 0);
        unsigned bal = __ballot_sync(0xffffffffu, m);
        if (lane == 0) mask_bits[t >> 5] = bal;
        if (m) {
            cnt++;
            lastidx = t;
            if (t > 0) {
                int ltc = (lt == -100) ? 0 : lt;
                int lp  = lab[t - 1];
                int lpc = (lp == -100) ? 0 : lp;
                numv += tbuf[lpc * KK + ltc] + emb[t * KK + ltc];
            }
        }
    }
    #pragma unroll
    for (int o = 16; o; o >>= 1) {
        numv += __shfl_xor_sync(0xffffffffu, numv, o);
        cnt  += __shfl_xor_sync(0xffffffffu, cnt,  o);
        lastidx = max(lastidx, __shfl_xor_sync(0xffffffffu, lastidx, o));
    }
    {
        int l0  = lab[0];
        int l0c = (l0 == -100) ? 0 : l0;
        int se  = max(cnt - 1, 0);
        int le  = lab[se];
        int lec = (le == -100) ? 0 : le;
        numv += startT[l0c] + emb[l0c] + endT[lec];
    }

    // ---- alpha_0 in linear space, carried log-scale M ----
    float al = (lane < KK) ? (startT[lane] + emb[lane]) : -1e30f;
    float M = al;
    #pragma unroll
    for (int o = 16; o; o >>= 1)
        M = fmaxf(M, __shfl_xor_sync(0xffffffffu, M, o));
    float a = (lane < KK) ? __expf(al - M) : 0.0f;

    // ---- preload emission tile 0, prefetch tile 1 into registers ----
    #pragma unroll
    for (int k = 0; k < KK; k++)
        ebuf[0][k * 32 + lane] = emb[k * 32 + lane];

    float pf[KK];
    const int lasttile = lastidx / TILE;
    if (lasttile >= 1) {
        #pragma unroll
        for (int k = 0; k < KK; k++)
            pf[k] = __ldg(&emb[TILEF + k * 32 + lane]);
    }
    __syncwarp();   // ebuf[0] + mask_bits visible

    // ---- forward scan over tiles ----
    for (int tb = 0; tb <= lasttile; tb++) {
        const float* eb = ebuf[tb & 1];
        const int t0 = tb * TILE;
        const int tstart = (t0 == 0) ? 1 : t0;
        const int tend = min(lastidx, t0 + TILE - 1);
        unsigned mword = mask_bits[tb];

        for (int t = tstart; t <= tend; ++t) {
            float e = (lane < KK) ? eb[(t - t0) * KK + lane] : 0.0f;
            float aold = a;

            float s0, s1, s2, s3;
            {
                float r;
                r = __shfl_sync(0xffffffffu, aold, 0);  s0 = r * w[0];
                r = __shfl_sync(0xffffffffu, aold, 1);  s1 = r * w[1];
                r = __shfl_sync(0xffffffffu, aold, 2);  s2 = r * w[2];
                r = __shfl_sync(0xffffffffu, aold, 3);  s3 = r * w[3];
                r = __shfl_sync(0xffffffffu, aold, 4);  s0 = fmaf(r, w[4],  s0);
                r = __shfl_sync(0xffffffffu, aold, 5);  s1 = fmaf(r, w[5],  s1);
                r = __shfl_sync(0xffffffffu, aold, 6);  s2 = fmaf(r, w[6],  s2);
                r = __shfl_sync(0xffffffffu, aold, 7);  s3 = fmaf(r, w[7],  s3);
                r = __shfl_sync(0xffffffffu, aold, 8);  s0 = fmaf(r, w[8],  s0);
                r = __shfl_sync(0xffffffffu, aold, 9);  s1 = fmaf(r, w[9],  s1);
                r = __shfl_sync(0xffffffffu, aold, 10); s2 = fmaf(r, w[10], s2);
                r = __shfl_sync(0xffffffffu, aold, 11); s3 = fmaf(r, w[11], s3);
                r = __shfl_sync(0xffffffffu, aold, 12); s0 = fmaf(r, w[12], s0);
                r = __shfl_sync(0xffffffffu, aold, 13); s1 = fmaf(r, w[13], s1);
                r = __shfl_sync(0xffffffffu, aold, 14); s2 = fmaf(r, w[14], s2);
                r = __shfl_sync(0xffffffffu, aold, 15); s3 = fmaf(r, w[15], s3);
                r = __shfl_sync(0xffffffffu, aold, 16); s0 = fmaf(r, w[16], s0);
            }
            float s = (s0 + s1) + (s2 + s3);

            float g = __expf(e);
            float anew = s * g;
            bool m = (mword >> (t & 31)) & 1u;
            float asel = m ? anew : aold;

            if ((t & 7) == 0) {
                // renorm by exact power of two derived from max of previous alpha
                float mx;
                {
                    float r0 = __shfl_sync(0xffffffffu, aold, 0);
                    float r1 = __shfl_sync(0xffffffffu, aold, 1);
                    float r2 = __shfl_sync(0xffffffffu, aold, 2);
                    float r3 = __shfl_sync(0xffffffffu, aold, 3);
                    r0 = fmaxf(r0, __shfl_sync(0xffffffffu, aold, 4));
                    r1 = fmaxf(r1, __shfl_sync(0xffffffffu, aold, 5));
                    r2 = fmaxf(r2, __shfl_sync(0xffffffffu, aold, 6));
                    r3 = fmaxf(r3, __shfl_sync(0xffffffffu, aold, 7));
                    r0 = fmaxf(r0, __shfl_sync(0xffffffffu, aold, 8));
                    r1 = fmaxf(r1, __shfl_sync(0xffffffffu, aold, 9));
                    r2 = fmaxf(r2, __shfl_sync(0xffffffffu, aold, 10));
                    r3 = fmaxf(r3, __shfl_sync(0xffffffffu, aold, 11));
                    r0 = fmaxf(r0, __shfl_sync(0xffffffffu, aold, 12));
                    r1 = fmaxf(r1, __shfl_sync(0xffffffffu, aold, 13));
                    r2 = fmaxf(r2, __shfl_sync(0xffffffffu, aold, 14));
                    r3 = fmaxf(r3, __shfl_sync(0xffffffffu, aold, 15));
                    r0 = fmaxf(r0, __shfl_sync(0xffffffffu, aold, 16));
                    mx = fmaxf(fmaxf(r0, r1), fmaxf(r2, r3));
                }
                int e2 = (__float_as_int(mx) >> 23) - 127;      // floor(log2(mx))
                float scale = __int_as_float((127 - e2) << 23); // exact 2^-e2
                asel *= scale;
                M += (float)e2 * 0.6931471805599453f;
            }
            a = asel;
        }

        // retire prefetch tile (tb+1) into the other buffer, start tile (tb+2)
        if (tb + 1 <= lasttile) {
            float* ebn = ebuf[(tb + 1) & 1];
            #pragma unroll
            for (int k = 0; k < KK; k++)
                ebn[k * 32 + lane] = pf[k];
            __syncwarp();
            if (tb + 2 <= lasttile) {
                const float* src = emb + (size_t)(tb + 2) * TILEF;
                #pragma unroll
                for (int k = 0; k < KK; k++)
                    pf[k] = __ldg(&src[k * 32 + lane]);
            }
        }
    }

    // ---- log_z = M + log( sum_j a_j * exp(end_j) ) ----
    float zterm = (lane < KK) ? a * __expf(endT[lane]) : 0.0f;
    #pragma unroll
    for (int o = 16; o; o >>= 1)
        zterm += __shfl_xor_sync(0xffffffffu, zterm, o);
    float logz = M + __logf(zterm);

    if (lane == 0)
        atomicAdd(out, (logz - numv) * (1.0f / (float)BB));  // -mean(llh)
}

extern "C" void kernel_launch(void* const* d_in, const int* in_sizes, int n_in,
                              void* d_out, int out_size)
{
    const float* em  = (const float*)d_in[0];
    const float* st  = (const float*)d_in[1];
    const float* en  = (const float*)d_in[2];
    const float* tr  = (const float*)d_in[3];
    const int*   lab = (const int*)d_in[4];
    const int*   att = (const int*)d_in[5];
    float* out = (float*)d_out;

    int copy = (out_size > in_sizes[0]) ? 1 : 0;

    cudaMemsetAsync(d_out, 0, sizeof(float), 0);
    crf_kernel<<<BB, 128>>>(em, st, en, tr, lab, att, out, copy);
}

// round 3
// speedup vs baseline: 3.1964x; 1.7008x over previous
#include <cuda_runtime.h>

// Problem constants (B, S, K) = (512, 2048, 17)
#define BB 512
#define SS 2048
#define KK 17
#define SK (SS * KK)
#define TILE 32            // scan steps per emission tile
#define TILEF (TILE * KK)  // 544 floats = 2176 B per tile

__device__ float g_part[BB];   // per-sequence (logZ - numerator)

__device__ __forceinline__ void cp16(void* smem, const void* gmem) {
    unsigned s = (unsigned)__cvta_generic_to_shared(smem);
    asm volatile("cp.async.cg.shared.global [%0], [%1], 16;\n" :: "r"(s), "l"(gmem));
}
#define CP_COMMIT() asm volatile("cp.async.commit_group;\n" ::: "memory")
#define CP_WAIT1()  asm volatile("cp.async.wait_group 1;\n" ::: "memory")

// copy one 544-float tile (136 x 16B) global -> shared via cp.async
__device__ __forceinline__ void load_tile(float* dst, const float* src, int lane) {
    #pragma unroll
    for (int r = 0; r < 4; r++)
        cp16(dst + (lane + 32 * r) * 4, src + (lane + 32 * r) * 4);
    if (lane < 8)
        cp16(dst + (128 + lane) * 4, src + (128 + lane) * 4);
}

__global__ __launch_bounds__(128) void crf_kernel(
    const float* __restrict__ em,      // [B,S,K]
    const float* __restrict__ startT,  // [K]
    const float* __restrict__ endT,    // [K]
    const float* __restrict__ trans,   // [K,K]
    const int*   __restrict__ labels,  // [B,S]
    const int*   __restrict__ attn,    // [B,S]
    float* __restrict__ out,           // [0]=loss, [1..]=emissions copy
    int copy_emissions)
{
    const int b   = blockIdx.x;
    const int tid = threadIdx.x;
    const float* emb = em + (size_t)b * SK;
    const int*   lab = labels + (size_t)b * SS;
    const int*   msk = attn   + (size_t)b * SS;

    // --- warps 1..3: stream-copy this sequence's emissions into the output ---
    if (tid >= 32) {
        if (copy_emissions) {
            const float4* s4 = (const float4*)emb;
            float* dst = out + 1 + (size_t)b * SK;   // 4B-aligned only -> scalar stores
            #pragma unroll 4
            for (int i = tid - 32; i < SK / 4; i += 96) {
                float4 v = s4[i];
                dst[4 * i + 0] = v.x;
                dst[4 * i + 1] = v.y;
                dst[4 * i + 2] = v.z;
                dst[4 * i + 3] = v.w;
            }
        }
        return;
    }

    // --- warp 0: numerator + forward scan ---
    const int lane = tid;

    __shared__ float    tbuf[KK * KK];                     // raw transitions
    __shared__ __align__(16) float ebuf[2][TILEF];         // emission tile double-buffer
    __shared__ unsigned mask_bits[SS / 32];

    for (int i = lane; i < KK * KK; i += 32)
        tbuf[i] = trans[i];
    __syncwarp();

    // exp(transitions) column for this lane's state j
    float w[KK];
    #pragma unroll
    for (int i = 0; i < KK; i++)
        w[i] = (lane < KK) ? __expf(tbuf[i * KK + lane]) : 0.0f;

    // ---- numerator pass + mask bit packing + seq-end stats ----
    float numv = 0.0f;
    int cnt = 0, lastidx = 0;
    for (int t = lane; t < SS; t += 32) {
        int lt = lab[t];
        int m  = (msk[t] != 0) && (lt >= 0);
        unsigned bal = __ballot_sync(0xffffffffu, m);
        if (lane == 0) mask_bits[t >> 5] = bal;
        if (m) {
            cnt++;
            lastidx = t;
            if (t > 0) {
                int ltc = (lt == -100) ? 0 : lt;
                int lp  = lab[t - 1];
                int lpc = (lp == -100) ? 0 : lp;
                numv += tbuf[lpc * KK + ltc] + emb[t * KK + ltc];
            }
        }
    }
    #pragma unroll
    for (int o = 16; o; o >>= 1) {
        numv += __shfl_xor_sync(0xffffffffu, numv, o);
        cnt  += __shfl_xor_sync(0xffffffffu, cnt,  o);
        lastidx = max(lastidx, __shfl_xor_sync(0xffffffffu, lastidx, o));
    }
    {
        int l0  = lab[0];
        int l0c = (l0 == -100) ? 0 : l0;
        int se  = max(cnt - 1, 0);
        int le  = lab[se];
        int lec = (le == -100) ? 0 : le;
        numv += startT[l0c] + emb[l0c] + endT[lec];
    }
    __syncwarp();   // mask_bits visible to all lanes

    // ---- alpha_0 in linear space, carried log-scale M ----
    float al = (lane < KK) ? (startT[lane] + emb[lane]) : -1e30f;
    float M = al;
    #pragma unroll
    for (int o = 16; o; o >>= 1)
        M = fmaxf(M, __shfl_xor_sync(0xffffffffu, M, o));
    float a = (lane < KK) ? __expf(al - M) : 0.0f;

    const int lasttile = lastidx / TILE;

    // prologue: async-load tiles 0 and 1 (2 committed groups invariant)
    load_tile(ebuf[0], emb, lane);
    CP_COMMIT();
    if (lasttile >= 1)
        load_tile(ebuf[1], emb + TILEF, lane);
    CP_COMMIT();

    // ---- forward scan over uniform 32-step tiles ----
    for (int tb = 0; tb <= lasttile; tb++) {
        CP_WAIT1();            // tile tb complete (<=1 group pending)
        __syncwarp();          // cross-lane visibility of cp.async data

        const float* eb = ebuf[tb & 1];
        unsigned mword = mask_bits[tb];
        if (tb == 0) mword &= ~1u;      // step t=0 does not exist

        #pragma unroll 8
        for (int tt = 0; tt < TILE; ++tt) {
            float e = eb[tt * KK + lane];   // lanes>=17 read other data; harmless
            float g = __expf(e);

            // broadcast previous alpha into 17 independent registers
            float rr[KK];
            #pragma unroll
            for (int i = 0; i < KK; i++)
                rr[i] = __shfl_sync(0xffffffffu, a, i);

            float s0 = rr[0] * w[0];
            float s1 = rr[1] * w[1];
            float s2 = rr[2] * w[2];
            float s3 = rr[3] * w[3];
            s0 = fmaf(rr[4],  w[4],  s0);
            s1 = fmaf(rr[5],  w[5],  s1);
            s2 = fmaf(rr[6],  w[6],  s2);
            s3 = fmaf(rr[7],  w[7],  s3);
            s0 = fmaf(rr[8],  w[8],  s0);
            s1 = fmaf(rr[9],  w[9],  s1);
            s2 = fmaf(rr[10], w[10], s2);
            s3 = fmaf(rr[11], w[11], s3);
            s0 = fmaf(rr[12], w[12], s0);
            s1 = fmaf(rr[13], w[13], s1);
            s2 = fmaf(rr[14], w[14], s2);
            s3 = fmaf(rr[15], w[15], s3);
            s0 = fmaf(rr[16], w[16], s0);
            float s = (s0 + s1) + (s2 + s3);

            bool m = (mword >> tt) & 1u;
            float anew = s * g;
            a = m ? anew : a;

            if ((tt & 7) == 0) {
                // renorm by exact power of two from max(previous alpha) = max(rr)
                float m0 = fmaxf(rr[0],  rr[1]);
                float m1 = fmaxf(rr[2],  rr[3]);
                float m2 = fmaxf(rr[4],  rr[5]);
                float m3 = fmaxf(rr[6],  rr[7]);
                m0 = fmaxf(m0, fmaxf(rr[8],  rr[9]));
                m1 = fmaxf(m1, fmaxf(rr[10], rr[11]));
                m2 = fmaxf(m2, fmaxf(rr[12], rr[13]));
                m3 = fmaxf(m3, fmaxf(rr[14], rr[15]));
                float mx = fmaxf(fmaxf(m0, m1), fmaxf(fmaxf(m2, m3), rr[16]));
                int e2 = (__float_as_int(mx) >> 23) - 127;       // floor(log2 mx)
                float scale = __int_as_float((127 - e2) << 23);  // exact 2^-e2
                a *= scale;
                M += (float)e2 * 0.6931471805599453f;
            }
        }

        // start async load of tile tb+2, keep 2-group invariant
        if (tb + 2 <= lasttile)
            load_tile(ebuf[tb & 1], emb + (size_t)(tb + 2) * TILEF, lane);
        CP_COMMIT();
    }

    // ---- log_z = M + log( sum_j a_j * exp(end_j) ) ----
    float zterm = (lane < KK) ? a * __expf(endT[lane]) : 0.0f;
    #pragma unroll
    for (int o = 16; o; o >>= 1)
        zterm += __shfl_xor_sync(0xffffffffu, zterm, o);
    float logz = M + __logf(zterm);

    if (lane == 0)
        g_part[b] = logz - numv;
}

__global__ void reduce_kernel(float* __restrict__ out)
{
    __shared__ float sh[128];
    int t = threadIdx.x;
    float v = 0.0f;
    #pragma unroll
    for (int i = 0; i < BB / 128; i++)
        v += g_part[t + 128 * i];
    sh[t] = v;
    __syncthreads();
    #pragma unroll
    for (int s2 = 64; s2; s2 >>= 1) {
        if (t < s2) sh[t] += sh[t + s2];
        __syncthreads();
    }
    if (t == 0) out[0] = sh[0] * (1.0f / (float)BB);
}

extern "C" void kernel_launch(void* const* d_in, const int* in_sizes, int n_in,
                              void* d_out, int out_size)
{
    const float* em  = (const float*)d_in[0];
    const float* st  = (const float*)d_in[1];
    const float* en  = (const float*)d_in[2];
    const float* tr  = (const float*)d_in[3];
    const int*   lab = (const int*)d_in[4];
    const int*   att = (const int*)d_in[5];
    float* out = (float*)d_out;

    int copy = (out_size > in_sizes[0]) ? 1 : 0;

    crf_kernel<<<BB, 128>>>(em, st, en, tr, lab, att, out, copy);
    reduce_kernel<<<1, 128>>>(out);
}